// round 4
// baseline (speedup 1.0000x reference)
#include <cuda_runtime.h>
#include <math.h>
#include <stdint.h>

// Problem constants (fixed shapes from the reference)
#define NN 50000
#define EE 600000
#define DD 128
#define GG 8
#define GN_EPS 1e-5f
#define MTILE 128

// ---------------- scratch (device globals; no cudaMalloc allowed) ----------
__device__ float g_agg[NN * DD];     // gathered mean, tf32-rounded
__device__ float g_xtf[NN * DD];     // x rounded to tf32
__device__ float g_wt[DD * 256];     // fused weights [n][k0..255] tf32-rounded
__device__ float g_f[NN * DD];       // post-GELU features
__device__ float g_sum[GG * DD];
__device__ float g_sumsq[GG * DD];
__device__ float g_cnt[GG];
__device__ float g_tmean[GG * DD];
__device__ float g_tscale[GG * DD];
__device__ int   g_degi[NN];
__device__ int   g_off[NN];
__device__ int   g_cur[NN];
__device__ int   g_csr[EE];

// ---------------- helpers ----------------
__device__ __forceinline__ uint32_t smem_u32(const void* p) {
    uint32_t a;
    asm("{ .reg .u64 t; cvta.to.shared.u64 t, %1; cvt.u32.u64 %0, t; }" : "=r"(a) : "l"(p));
    return a;
}
__device__ __forceinline__ void red_add_v2(float* p, float2 v) {
    size_t gp = __cvta_generic_to_global(p);
    asm volatile("red.global.add.v2.f32 [%0], {%1,%2};"
                 :: "l"(gp), "f"(v.x), "f"(v.y) : "memory");
}
__device__ __forceinline__ float gelu_exact(float v) {
    return 0.5f * v * (1.0f + erff(v * 0.70710678118654752f));
}
__device__ __forceinline__ float cvt_tf32(float f) {
    uint32_t u;
    asm("cvt.rna.satfinite.tf32.f32 %0, %1;" : "=r"(u) : "f"(f));
    return __uint_as_float(u);
}
__device__ __forceinline__ float4 cvt_tf32x4(float4 v) {
    return make_float4(cvt_tf32(v.x), cvt_tf32(v.y), cvt_tf32(v.z), cvt_tf32(v.w));
}
__device__ __forceinline__ void cp16(uint32_t dst, const void* src, bool pred) {
    int sz = pred ? 16 : 0;
    asm volatile("cp.async.cg.shared.global [%0], [%1], 16, %2;"
                 :: "r"(dst), "l"(src), "r"(sz) : "memory");
}
__device__ __forceinline__ void cp_commit() {
    asm volatile("cp.async.commit_group;" ::: "memory");
}
template <int N>
__device__ __forceinline__ void cp_wait() {
    asm volatile("cp.async.wait_group %0;" :: "n"(N) : "memory");
}
__device__ __forceinline__ void mma_tf32(float* d, const uint32_t* a, const uint32_t* b) {
    asm volatile("mma.sync.aligned.m16n8k8.row.col.f32.tf32.tf32.f32 "
                 "{%0,%1,%2,%3}, {%4,%5,%6,%7}, {%8,%9}, {%0,%1,%2,%3};"
                 : "+f"(d[0]), "+f"(d[1]), "+f"(d[2]), "+f"(d[3])
                 : "r"(a[0]), "r"(a[1]), "r"(a[2]), "r"(a[3]), "r"(b[0]), "r"(b[1]));
}

// ---------------- K1: zero small scratch ----------------
__global__ void kInit() {
    int i = blockIdx.x * blockDim.x + threadIdx.x;
    if (i < NN) g_degi[i] = 0;
    if (i < GG * DD) { g_sum[i] = 0.f; g_sumsq[i] = 0.f; }
    if (i < GG) g_cnt[i] = 0.f;
}

// ---------------- K1b: per-graph node counts ----------------
__global__ void kCnt(const int* __restrict__ batch) {
    __shared__ float h[GG];
    if (threadIdx.x < GG) h[threadIdx.x] = 0.f;
    __syncthreads();
    int i = blockIdx.x * blockDim.x + threadIdx.x;
    if (i < NN) atomicAdd(&h[batch[i]], 1.f);
    __syncthreads();
    if (threadIdx.x < GG) atomicAdd(&g_cnt[threadIdx.x], h[threadIdx.x]);
}

// ---------------- K2a: in-degree histogram ----------------
__global__ void kDeg(const int* __restrict__ ei, int E) {
    int e = blockIdx.x * blockDim.x + threadIdx.x;
    if (e < E) atomicAdd(&g_degi[__ldg(ei + E + e)], 1);
}

// ---------------- K2b: exclusive prefix scan (single block) ----------------
__global__ void __launch_bounds__(1024) kScan() {
    __shared__ int part[1024];
    const int C = (NN + 1023) / 1024;
    int t = threadIdx.x;
    int base = t * C;
    int s = 0;
    for (int k = 0; k < C; k++) {
        int i = base + k;
        if (i < NN) s += g_degi[i];
    }
    part[t] = s;
    __syncthreads();
    for (int off = 1; off < 1024; off <<= 1) {
        int v = (t >= off) ? part[t - off] : 0;
        __syncthreads();
        part[t] += v;
        __syncthreads();
    }
    int run = (t > 0) ? part[t - 1] : 0;
    for (int k = 0; k < C; k++) {
        int i = base + k;
        if (i < NN) {
            g_off[i] = run;
            g_cur[i] = run;
            run += g_degi[i];
        }
    }
}

// ---------------- K2c: counting-sort edges into CSR ----------------
__global__ void kBuildCSR(const int* __restrict__ ei, int E) {
    int e = blockIdx.x * blockDim.x + threadIdx.x;
    if (e >= E) return;
    int dst = __ldg(ei + E + e);
    int pos = atomicAdd(&g_cur[dst], 1);
    g_csr[pos] = __ldg(ei + e);
}

// ---------------- K2d: warp-per-node gather, scale, tf32-round -------------
__global__ void kGather(const float* __restrict__ x) {
    int node = (blockIdx.x * blockDim.x + threadIdx.x) >> 5;
    int lane = threadIdx.x & 31;
    if (node >= NN) return;
    int o0 = __ldg(&g_off[node]);
    int d  = __ldg(&g_degi[node]);
    float4 acc = make_float4(0.f, 0.f, 0.f, 0.f);
#pragma unroll 4
    for (int j = 0; j < d; j++) {
        int nb = __ldg(&g_csr[o0 + j]);
        float4 v = ((const float4*)x)[(size_t)nb * 32 + lane];
        acc.x += v.x; acc.y += v.y; acc.z += v.z; acc.w += v.w;
    }
    float iv = 1.0f / fmaxf((float)d, 1.0f);
    acc.x *= iv; acc.y *= iv; acc.z *= iv; acc.w *= iv;
    ((float4*)g_agg)[(size_t)node * 32 + lane] = cvt_tf32x4(acc);
}

// ---------------- K2e: x -> tf32 rounded copy ----------------
__global__ void kPrepX(const float* __restrict__ x) {
    int i4 = blockIdx.x * blockDim.x + threadIdx.x;
    if (i4 >= NN * 32) return;
    ((float4*)g_xtf)[i4] = cvt_tf32x4(((const float4*)x)[i4]);
}

// ---------------- K2f: fuse + round weights into g_wt[n][0..255] ----------
__global__ void kPrepW(const float* __restrict__ Wl, const float* __restrict__ Wr) {
    int i4 = blockIdx.x * blockDim.x + threadIdx.x;
    if (i4 >= DD * 64) return;
    int n = i4 >> 6, c4 = i4 & 63;
    float4 v = (c4 < 32) ? ((const float4*)Wl)[n * 32 + c4]
                         : ((const float4*)Wr)[n * 32 + (c4 - 32)];
    ((float4*)g_wt)[i4] = cvt_tf32x4(v);
}

// ---------------- K3: tf32 mma.sync GEMM 128x128 tile, K=256 ---------------
#define ASTRIDE 36
#define BUF_BYTES (128 * ASTRIDE * 4)
#define SMEM_G (4 * BUF_BYTES)

__global__ void __launch_bounds__(256) kGemm(const float* __restrict__ bl,
                                             const int* __restrict__ batch) {
    extern __shared__ char smem[];
    uint32_t sbase = smem_u32(smem);
    int tid = threadIdx.x, wid = tid >> 5, lane = tid & 31;
    int gid = lane >> 2, tidg = lane & 3;
    int wm = wid & 1, wn = wid >> 1;
    int row0 = blockIdx.x * MTILE;

    auto issue = [&](int c, int b) {
        const float* Asrc = (c < 4) ? g_agg : g_xtf;
#pragma unroll
        for (int i = 0; i < 4; i++) {
            int idx = i * 256 + tid;
            int m = idx >> 3, c4 = idx & 7;
            int gr = row0 + m;
            bool ok = gr < NN;
            const float4* src = (const float4*)Asrc + (size_t)(ok ? gr : 0) * 32 + (c & 3) * 8 + c4;
            cp16(sbase + b * BUF_BYTES + (m * ASTRIDE + c4 * 4) * 4, src, ok);
        }
#pragma unroll
        for (int i = 0; i < 4; i++) {
            int idx = i * 256 + tid;
            int n = idx >> 3, c4 = idx & 7;
            const float4* src = (const float4*)g_wt + n * 64 + c * 8 + c4;
            cp16(sbase + (2 + b) * BUF_BYTES + (n * ASTRIDE + c4 * 4) * 4, src, true);
        }
        cp_commit();
    };

    float acc[4][4][4];
#pragma unroll
    for (int mf = 0; mf < 4; mf++)
#pragma unroll
        for (int nf = 0; nf < 4; nf++)
#pragma unroll
            for (int i = 0; i < 4; i++) acc[mf][nf][i] = 0.f;

    issue(0, 0);
    for (int c = 0; c < 8; c++) {
        int b = c & 1;
        if (c < 7) issue(c + 1, b ^ 1);
        if (c < 7) cp_wait<1>(); else cp_wait<0>();
        __syncthreads();

        const float* sA = (const float*)(smem + b * BUF_BYTES);
        const float* sB = (const float*)(smem + (2 + b) * BUF_BYTES);
#pragma unroll
        for (int ks = 0; ks < 32; ks += 8) {
            uint32_t a[4][4], bf[4][2];
#pragma unroll
            for (int mf = 0; mf < 4; mf++) {
                int r = wm * 64 + mf * 16 + gid;
                a[mf][0] = __float_as_uint(sA[r * ASTRIDE + ks + tidg]);
                a[mf][1] = __float_as_uint(sA[(r + 8) * ASTRIDE + ks + tidg]);
                a[mf][2] = __float_as_uint(sA[r * ASTRIDE + ks + tidg + 4]);
                a[mf][3] = __float_as_uint(sA[(r + 8) * ASTRIDE + ks + tidg + 4]);
            }
#pragma unroll
            for (int nf = 0; nf < 4; nf++) {
                int n = wn * 32 + nf * 8 + gid;
                bf[nf][0] = __float_as_uint(sB[n * ASTRIDE + ks + tidg]);
                bf[nf][1] = __float_as_uint(sB[n * ASTRIDE + ks + tidg + 4]);
            }
#pragma unroll
            for (int mf = 0; mf < 4; mf++)
#pragma unroll
                for (int nf = 0; nf < 4; nf++)
                    mma_tf32(acc[mf][nf], a[mf], bf[nf]);
        }
        __syncthreads();
    }

    // Epilogue: bias + exact GELU -> g_f, fused GraphNorm sum/sumsq accumulation
    int rlast = min(row0 + 127, NN - 1);
    int g0 = __ldg(batch + row0);
    bool uni = (__ldg(batch + rlast) == g0);

    float2 s[4], q[4];
#pragma unroll
    for (int nf = 0; nf < 4; nf++) { s[nf] = make_float2(0.f, 0.f); q[nf] = make_float2(0.f, 0.f); }

#pragma unroll
    for (int nf = 0; nf < 4; nf++) {
        int col = wn * 32 + nf * 8 + 2 * tidg;
        float2 bv = *(const float2*)(bl + col);
#pragma unroll
        for (int mf = 0; mf < 4; mf++) {
#pragma unroll
            for (int half = 0; half < 2; half++) {
                int r = row0 + wm * 64 + mf * 16 + gid + half * 8;
                if (r < NN) {
                    float2 f;
                    f.x = gelu_exact(acc[mf][nf][2 * half + 0] + bv.x);
                    f.y = gelu_exact(acc[mf][nf][2 * half + 1] + bv.y);
                    *(float2*)(g_f + (size_t)r * DD + col) = f;
                    if (uni) {
                        s[nf].x += f.x; s[nf].y += f.y;
                        q[nf].x += f.x * f.x; q[nf].y += f.y * f.y;
                    } else {
                        int g = __ldg(batch + r);
                        atomicAdd(&g_sum[g * DD + col], f.x);
                        atomicAdd(&g_sum[g * DD + col + 1], f.y);
                        atomicAdd(&g_sumsq[g * DD + col], f.x * f.x);
                        atomicAdd(&g_sumsq[g * DD + col + 1], f.y * f.y);
                    }
                }
            }
        }
    }
    if (uni) {
        // reduce across the 8 gid groups (lanes stride 4) before the global RED
#pragma unroll
        for (int nf = 0; nf < 4; nf++) {
#pragma unroll
            for (int d = 4; d < 32; d <<= 1) {
                s[nf].x += __shfl_xor_sync(0xFFFFFFFF, s[nf].x, d);
                s[nf].y += __shfl_xor_sync(0xFFFFFFFF, s[nf].y, d);
                q[nf].x += __shfl_xor_sync(0xFFFFFFFF, q[nf].x, d);
                q[nf].y += __shfl_xor_sync(0xFFFFFFFF, q[nf].y, d);
            }
        }
        if (gid == 0) {
#pragma unroll
            for (int nf = 0; nf < 4; nf++) {
                int col = wn * 32 + nf * 8 + 2 * tidg;
                red_add_v2(&g_sum[g0 * DD + col], s[nf]);
                red_add_v2(&g_sumsq[g0 * DD + col], q[nf]);
            }
        }
    }
}

// ---------------- K4: per-(graph,channel) stats ----------------
__global__ void kStats(const float* __restrict__ mean_scale) {
    int i = blockIdx.x * blockDim.x + threadIdx.x;
    if (i >= GG * DD) return;
    int c = i & 127;
    int g = i >> 7;
    float cnt = fmaxf(g_cnt[g], 1.0f);
    float m   = g_sum[i] / cnt;
    float ex2 = g_sumsq[i] / cnt;
    float sc  = mean_scale[c];
    float var = ex2 - (2.0f * sc - sc * sc) * m * m;
    g_tmean[i]  = sc * m;
    g_tscale[i] = rsqrtf(fmaxf(var, 0.0f) + GN_EPS);
}

// ---------------- K5: finalize out = norm(f)*w + b + x ----------------
__global__ void kFinal(const float* __restrict__ x,
                       const int* __restrict__ batch,
                       const float* __restrict__ gw,
                       const float* __restrict__ gb,
                       float* __restrict__ out) {
    int i4 = blockIdx.x * blockDim.x + threadIdx.x;
    if (i4 >= NN * 32) return;
    int row = i4 >> 5;
    int c4  = i4 & 31;
    int g = __ldg(batch + row);
    float4 f  = ((const float4*)g_f)[i4];
    float4 xv = ((const float4*)x)[i4];
    float4 tm = ((const float4*)g_tmean)[g * 32 + c4];
    float4 ts = ((const float4*)g_tscale)[g * 32 + c4];
    float4 wv = ((const float4*)gw)[c4];
    float4 bv = ((const float4*)gb)[c4];
    float4 o;
    o.x = (f.x - tm.x) * ts.x * wv.x + bv.x + xv.x;
    o.y = (f.y - tm.y) * ts.y * wv.y + bv.y + xv.y;
    o.z = (f.z - tm.z) * ts.z * wv.z + bv.z + xv.z;
    o.w = (f.w - tm.w) * ts.w * wv.w + bv.w + xv.w;
    ((float4*)out)[i4] = o;
}

// ---------------- launch ----------------
extern "C" void kernel_launch(void* const* d_in, const int* in_sizes, int n_in,
                              void* d_out, int out_size) {
    const float* x     = (const float*)d_in[0];
    const int*   ei    = (const int*)d_in[1];
    const int*   batch = (const int*)d_in[2];
    int E = in_sizes[1] / 2;

    int wi = (in_sizes[3] == DD * DD) ? 3 : 4;
    const float* Wl = (const float*)d_in[wi + 0];
    const float* bl = (const float*)d_in[wi + 1];
    const float* Wr = (const float*)d_in[wi + 2];
    const float* gw = (const float*)d_in[wi + 3];
    const float* gb = (const float*)d_in[wi + 4];
    const float* ms = (const float*)d_in[wi + 5];
    float* out = (float*)d_out;

    cudaFuncSetAttribute(kGemm, cudaFuncAttributeMaxDynamicSharedMemorySize, SMEM_G);

    kInit<<<(NN + 255) / 256, 256>>>();
    kCnt<<<(NN + 255) / 256, 256>>>(batch);
    kDeg<<<(E + 255) / 256, 256>>>(ei, E);
    kScan<<<1, 1024>>>();
    kBuildCSR<<<(E + 255) / 256, 256>>>(ei, E);
    kGather<<<(NN * 32 + 255) / 256, 256>>>(x);
    kPrepX<<<(NN * 32 + 255) / 256, 256>>>(x);
    kPrepW<<<(DD * 64 + 255) / 256, 256>>>(Wl, Wr);
    kGemm<<<(NN + MTILE - 1) / MTILE, 256, SMEM_G>>>(bl, batch);
    kStats<<<(GG * DD + 255) / 256, 256>>>(ms);
    kFinal<<<(NN * 32 + 255) / 256, 256>>>(x, batch, gw, gb, out);
}

// round 5
// speedup vs baseline: 1.6757x; 1.6757x over previous
#include <cuda_runtime.h>
#include <math.h>
#include <stdint.h>

// Problem constants (fixed shapes from the reference)
#define NN 50000
#define EE 600000
#define DD 128
#define GG 8
#define GN_EPS 1e-5f
#define MTILE 128
#define NB ((NN + 1023) / 1024)   // 49 scan blocks

// ---------------- scratch (device globals; no cudaMalloc allowed) ----------
__device__ float g_agg[NN * DD];     // gathered mean, tf32-rounded
__device__ float g_xtf[NN * DD];     // x rounded to tf32
__device__ float g_wt[DD * 256];     // fused weights [n][k0..255] tf32-rounded
__device__ float g_f[NN * DD];       // post-GELU features
__device__ float g_sum[GG * DD];
__device__ float g_sumsq[GG * DD];
__device__ float g_cnt[GG];
__device__ float g_tmean[GG * DD];
__device__ float g_tscale[GG * DD];
__device__ int   g_degi[NN];
__device__ int   g_off[NN];
__device__ int   g_cur[NN];
__device__ int   g_csr[EE];
__device__ int   g_bsum[NB];
__device__ int   g_bscan[NB];

// ---------------- helpers ----------------
__device__ __forceinline__ uint32_t smem_u32(const void* p) {
    uint32_t a;
    asm("{ .reg .u64 t; cvta.to.shared.u64 t, %1; cvt.u32.u64 %0, t; }" : "=r"(a) : "l"(p));
    return a;
}
__device__ __forceinline__ void red_add_v2(float* p, float2 v) {
    size_t gp = __cvta_generic_to_global(p);
    asm volatile("red.global.add.v2.f32 [%0], {%1,%2};"
                 :: "l"(gp), "f"(v.x), "f"(v.y) : "memory");
}
__device__ __forceinline__ float gelu_exact(float v) {
    return 0.5f * v * (1.0f + erff(v * 0.70710678118654752f));
}
__device__ __forceinline__ float cvt_tf32(float f) {
    uint32_t u;
    asm("cvt.rna.satfinite.tf32.f32 %0, %1;" : "=r"(u) : "f"(f));
    return __uint_as_float(u);
}
__device__ __forceinline__ float4 cvt_tf32x4(float4 v) {
    return make_float4(cvt_tf32(v.x), cvt_tf32(v.y), cvt_tf32(v.z), cvt_tf32(v.w));
}
__device__ __forceinline__ void cp16(uint32_t dst, const void* src, bool pred) {
    int sz = pred ? 16 : 0;
    asm volatile("cp.async.cg.shared.global [%0], [%1], 16, %2;"
                 :: "r"(dst), "l"(src), "r"(sz) : "memory");
}
__device__ __forceinline__ void cp_commit() {
    asm volatile("cp.async.commit_group;" ::: "memory");
}
template <int N>
__device__ __forceinline__ void cp_wait() {
    asm volatile("cp.async.wait_group %0;" :: "n"(N) : "memory");
}
__device__ __forceinline__ void mma_tf32(float* d, const uint32_t* a, const uint32_t* b) {
    asm volatile("mma.sync.aligned.m16n8k8.row.col.f32.tf32.tf32.f32 "
                 "{%0,%1,%2,%3}, {%4,%5,%6,%7}, {%8,%9}, {%0,%1,%2,%3};"
                 : "+f"(d[0]), "+f"(d[1]), "+f"(d[2]), "+f"(d[3])
                 : "r"(a[0]), "r"(a[1]), "r"(a[2]), "r"(a[3]), "r"(b[0]), "r"(b[1]));
}

// ---------------- K1: zero small scratch ----------------
__global__ void kInit() {
    int i = blockIdx.x * blockDim.x + threadIdx.x;
    if (i < NN) g_degi[i] = 0;
    if (i < GG * DD) { g_sum[i] = 0.f; g_sumsq[i] = 0.f; }
    if (i < GG) g_cnt[i] = 0.f;
}

// ---------------- K2: degree histogram + per-graph node counts -------------
__global__ void kDegCnt(const int* __restrict__ ei, const int* __restrict__ batch, int E) {
    __shared__ float h[GG];
    if (threadIdx.x < GG) h[threadIdx.x] = 0.f;
    __syncthreads();
    int i = blockIdx.x * blockDim.x + threadIdx.x;
    if (i < E) atomicAdd(&g_degi[__ldg(ei + E + i)], 1);
    if (i < NN) atomicAdd(&h[__ldg(batch + i)], 1.f);
    __syncthreads();
    if (threadIdx.x < GG) atomicAdd(&g_cnt[threadIdx.x], h[threadIdx.x]);
}

// ---------------- K3a: block-local exclusive scan ----------------
__global__ void __launch_bounds__(1024) kScan1() {
    __shared__ int wsum[32];
    int lane = threadIdx.x & 31, w = threadIdx.x >> 5;
    int i = blockIdx.x * 1024 + threadIdx.x;
    int v = (i < NN) ? g_degi[i] : 0;
    int s = v;
#pragma unroll
    for (int d = 1; d < 32; d <<= 1) {
        int t = __shfl_up_sync(0xFFFFFFFF, s, d);
        if (lane >= d) s += t;
    }
    if (lane == 31) wsum[w] = s;
    __syncthreads();
    if (w == 0) {
        int t = wsum[lane];
#pragma unroll
        for (int d = 1; d < 32; d <<= 1) {
            int u = __shfl_up_sync(0xFFFFFFFF, t, d);
            if (lane >= d) t += u;
        }
        wsum[lane] = t;
    }
    __syncthreads();
    int excl = s - v + (w > 0 ? wsum[w - 1] : 0);
    if (i < NN) g_off[i] = excl;
    if (threadIdx.x == 1023) g_bsum[blockIdx.x] = wsum[31];
}

// ---------------- K3b: scan the 49 block totals ----------------
__global__ void kScan2() {
    int lane = threadIdx.x;   // one block, 64 threads
    int v = (lane < NB) ? g_bsum[lane] : 0;
    int s = v;
#pragma unroll
    for (int d = 1; d < 32; d <<= 1) {
        int t = __shfl_up_sync(0xFFFFFFFF, s, d);
        if ((lane & 31) >= d) s += t;
    }
    __shared__ int w0;
    if (lane == 31) w0 = s;
    __syncthreads();
    int excl = s - v + ((lane >= 32) ? w0 : 0);
    if (lane < NB) g_bscan[lane] = excl;
}

// ---------------- K3c: add block base, init cursors ----------------
__global__ void __launch_bounds__(1024) kScan3() {
    int i = blockIdx.x * 1024 + threadIdx.x;
    if (i >= NN) return;
    int o = g_off[i] + g_bscan[blockIdx.x];
    g_off[i] = o;
    g_cur[i] = o;
}

// ---------------- K4: counting-sort edges into CSR ----------------
__global__ void kBuildCSR(const int* __restrict__ ei, int E) {
    int e = blockIdx.x * blockDim.x + threadIdx.x;
    if (e >= E) return;
    int dst = __ldg(ei + E + e);
    int pos = atomicAdd(&g_cur[dst], 1);
    g_csr[pos] = __ldg(ei + e);
}

// ---------------- K5: warp-per-node gather, scale, tf32-round -------------
__global__ void kGather(const float* __restrict__ x) {
    int node = (blockIdx.x * blockDim.x + threadIdx.x) >> 5;
    int lane = threadIdx.x & 31;
    if (node >= NN) return;
    int o0 = __ldg(&g_off[node]);
    int d  = __ldg(&g_degi[node]);
    float4 acc = make_float4(0.f, 0.f, 0.f, 0.f);
#pragma unroll 4
    for (int j = 0; j < d; j++) {
        int nb = __ldg(&g_csr[o0 + j]);
        float4 v = ((const float4*)x)[(size_t)nb * 32 + lane];
        acc.x += v.x; acc.y += v.y; acc.z += v.z; acc.w += v.w;
    }
    float iv = 1.0f / fmaxf((float)d, 1.0f);
    acc.x *= iv; acc.y *= iv; acc.z *= iv; acc.w *= iv;
    ((float4*)g_agg)[(size_t)node * 32 + lane] = cvt_tf32x4(acc);
}

// ---------------- K6: x -> tf32 copy + weight fuse (one launch) ------------
__global__ void kPrep(const float* __restrict__ x,
                      const float* __restrict__ Wl, const float* __restrict__ Wr) {
    int i4 = blockIdx.x * blockDim.x + threadIdx.x;
    if (i4 < NN * 32) {
        ((float4*)g_xtf)[i4] = cvt_tf32x4(((const float4*)x)[i4]);
    } else if (i4 < NN * 32 + DD * 64) {
        int j = i4 - NN * 32;
        int n = j >> 6, c4 = j & 63;
        float4 v = (c4 < 32) ? ((const float4*)Wl)[n * 32 + c4]
                             : ((const float4*)Wr)[n * 32 + (c4 - 32)];
        ((float4*)g_wt)[j] = cvt_tf32x4(v);
    }
}

// ---------------- K7: tf32 mma.sync GEMM 128x128 tile, K=256 ---------------
#define ASTRIDE 36
#define BUF_BYTES (128 * ASTRIDE * 4)
#define SMEM_G (4 * BUF_BYTES)

__global__ void __launch_bounds__(256) kGemm(const float* __restrict__ bl,
                                             const int* __restrict__ batch) {
    extern __shared__ char smem[];
    uint32_t sbase = smem_u32(smem);
    int tid = threadIdx.x, wid = tid >> 5, lane = tid & 31;
    int gid = lane >> 2, tidg = lane & 3;
    int wm = wid & 1, wn = wid >> 1;
    int row0 = blockIdx.x * MTILE;

    auto issue = [&](int c, int b) {
        const float* Asrc = (c < 4) ? g_agg : g_xtf;
#pragma unroll
        for (int i = 0; i < 4; i++) {
            int idx = i * 256 + tid;
            int m = idx >> 3, c4 = idx & 7;
            int gr = row0 + m;
            bool ok = gr < NN;
            const float4* src = (const float4*)Asrc + (size_t)(ok ? gr : 0) * 32 + (c & 3) * 8 + c4;
            cp16(sbase + b * BUF_BYTES + (m * ASTRIDE + c4 * 4) * 4, src, ok);
        }
#pragma unroll
        for (int i = 0; i < 4; i++) {
            int idx = i * 256 + tid;
            int n = idx >> 3, c4 = idx & 7;
            const float4* src = (const float4*)g_wt + n * 64 + c * 8 + c4;
            cp16(sbase + (2 + b) * BUF_BYTES + (n * ASTRIDE + c4 * 4) * 4, src, true);
        }
        cp_commit();
    };

    float acc[4][4][4];
#pragma unroll
    for (int mf = 0; mf < 4; mf++)
#pragma unroll
        for (int nf = 0; nf < 4; nf++)
#pragma unroll
            for (int i = 0; i < 4; i++) acc[mf][nf][i] = 0.f;

    issue(0, 0);
    for (int c = 0; c < 8; c++) {
        int b = c & 1;
        if (c < 7) issue(c + 1, b ^ 1);
        if (c < 7) cp_wait<1>(); else cp_wait<0>();
        __syncthreads();

        const float* sA = (const float*)(smem + b * BUF_BYTES);
        const float* sB = (const float*)(smem + (2 + b) * BUF_BYTES);
#pragma unroll
        for (int ks = 0; ks < 32; ks += 8) {
            uint32_t a[4][4], bf[4][2];
#pragma unroll
            for (int mf = 0; mf < 4; mf++) {
                int r = wm * 64 + mf * 16 + gid;
                a[mf][0] = __float_as_uint(sA[r * ASTRIDE + ks + tidg]);
                a[mf][1] = __float_as_uint(sA[(r + 8) * ASTRIDE + ks + tidg]);
                a[mf][2] = __float_as_uint(sA[r * ASTRIDE + ks + tidg + 4]);
                a[mf][3] = __float_as_uint(sA[(r + 8) * ASTRIDE + ks + tidg + 4]);
            }
#pragma unroll
            for (int nf = 0; nf < 4; nf++) {
                int n = wn * 32 + nf * 8 + gid;
                bf[nf][0] = __float_as_uint(sB[n * ASTRIDE + ks + tidg]);
                bf[nf][1] = __float_as_uint(sB[n * ASTRIDE + ks + tidg + 4]);
            }
#pragma unroll
            for (int mf = 0; mf < 4; mf++)
#pragma unroll
                for (int nf = 0; nf < 4; nf++)
                    mma_tf32(acc[mf][nf], a[mf], bf[nf]);
        }
        __syncthreads();
    }

    // Epilogue: bias + exact GELU -> g_f, fused GraphNorm sum/sumsq
    int rlast = min(row0 + 127, NN - 1);
    int g0 = __ldg(batch + row0);
    bool uni = (__ldg(batch + rlast) == g0);

    float2 s[4], q[4];
#pragma unroll
    for (int nf = 0; nf < 4; nf++) { s[nf] = make_float2(0.f, 0.f); q[nf] = make_float2(0.f, 0.f); }

#pragma unroll
    for (int nf = 0; nf < 4; nf++) {
        int col = wn * 32 + nf * 8 + 2 * tidg;
        float2 bv = *(const float2*)(bl + col);
#pragma unroll
        for (int mf = 0; mf < 4; mf++) {
#pragma unroll
            for (int half = 0; half < 2; half++) {
                int r = row0 + wm * 64 + mf * 16 + gid + half * 8;
                if (r < NN) {
                    float2 f;
                    f.x = gelu_exact(acc[mf][nf][2 * half + 0] + bv.x);
                    f.y = gelu_exact(acc[mf][nf][2 * half + 1] + bv.y);
                    *(float2*)(g_f + (size_t)r * DD + col) = f;
                    if (uni) {
                        s[nf].x += f.x; s[nf].y += f.y;
                        q[nf].x += f.x * f.x; q[nf].y += f.y * f.y;
                    } else {
                        int g = __ldg(batch + r);
                        atomicAdd(&g_sum[g * DD + col], f.x);
                        atomicAdd(&g_sum[g * DD + col + 1], f.y);
                        atomicAdd(&g_sumsq[g * DD + col], f.x * f.x);
                        atomicAdd(&g_sumsq[g * DD + col + 1], f.y * f.y);
                    }
                }
            }
        }
    }
    if (uni) {
#pragma unroll
        for (int nf = 0; nf < 4; nf++) {
#pragma unroll
            for (int d = 4; d < 32; d <<= 1) {
                s[nf].x += __shfl_xor_sync(0xFFFFFFFF, s[nf].x, d);
                s[nf].y += __shfl_xor_sync(0xFFFFFFFF, s[nf].y, d);
                q[nf].x += __shfl_xor_sync(0xFFFFFFFF, q[nf].x, d);
                q[nf].y += __shfl_xor_sync(0xFFFFFFFF, q[nf].y, d);
            }
        }
        if (gid == 0) {
#pragma unroll
            for (int nf = 0; nf < 4; nf++) {
                int col = wn * 32 + nf * 8 + 2 * tidg;
                red_add_v2(&g_sum[g0 * DD + col], s[nf]);
                red_add_v2(&g_sumsq[g0 * DD + col], q[nf]);
            }
        }
    }
}

// ---------------- K8: per-(graph,channel) stats ----------------
__global__ void kStats(const float* __restrict__ mean_scale) {
    int i = blockIdx.x * blockDim.x + threadIdx.x;
    if (i >= GG * DD) return;
    int c = i & 127;
    int g = i >> 7;
    float cnt = fmaxf(g_cnt[g], 1.0f);
    float m   = g_sum[i] / cnt;
    float ex2 = g_sumsq[i] / cnt;
    float sc  = mean_scale[c];
    float var = ex2 - (2.0f * sc - sc * sc) * m * m;
    g_tmean[i]  = sc * m;
    g_tscale[i] = rsqrtf(fmaxf(var, 0.0f) + GN_EPS);
}

// ---------------- K9: finalize out = norm(f)*w + b + x ----------------
__global__ void kFinal(const float* __restrict__ x,
                       const int* __restrict__ batch,
                       const float* __restrict__ gw,
                       const float* __restrict__ gb,
                       float* __restrict__ out) {
    int i4 = blockIdx.x * blockDim.x + threadIdx.x;
    if (i4 >= NN * 32) return;
    int row = i4 >> 5;
    int c4  = i4 & 31;
    int g = __ldg(batch + row);
    float4 f  = ((const float4*)g_f)[i4];
    float4 xv = ((const float4*)x)[i4];
    float4 tm = ((const float4*)g_tmean)[g * 32 + c4];
    float4 ts = ((const float4*)g_tscale)[g * 32 + c4];
    float4 wv = ((const float4*)gw)[c4];
    float4 bv = ((const float4*)gb)[c4];
    float4 o;
    o.x = (f.x - tm.x) * ts.x * wv.x + bv.x + xv.x;
    o.y = (f.y - tm.y) * ts.y * wv.y + bv.y + xv.y;
    o.z = (f.z - tm.z) * ts.z * wv.z + bv.z + xv.z;
    o.w = (f.w - tm.w) * ts.w * wv.w + bv.w + xv.w;
    ((float4*)out)[i4] = o;
}

// ---------------- launch ----------------
extern "C" void kernel_launch(void* const* d_in, const int* in_sizes, int n_in,
                              void* d_out, int out_size) {
    const float* x     = (const float*)d_in[0];
    const int*   ei    = (const int*)d_in[1];
    const int*   batch = (const int*)d_in[2];
    int E = in_sizes[1] / 2;

    int wi = (in_sizes[3] == DD * DD) ? 3 : 4;
    const float* Wl = (const float*)d_in[wi + 0];
    const float* bl = (const float*)d_in[wi + 1];
    const float* Wr = (const float*)d_in[wi + 2];
    const float* gw = (const float*)d_in[wi + 3];
    const float* gb = (const float*)d_in[wi + 4];
    const float* ms = (const float*)d_in[wi + 5];
    float* out = (float*)d_out;

    cudaFuncSetAttribute(kGemm, cudaFuncAttributeMaxDynamicSharedMemorySize, SMEM_G);

    kInit<<<(NN + 255) / 256, 256>>>();
    kDegCnt<<<(E + 255) / 256, 256>>>(ei, batch, E);
    kScan1<<<NB, 1024>>>();
    kScan2<<<1, 64>>>();
    kScan3<<<NB, 1024>>>();
    kBuildCSR<<<(E + 255) / 256, 256>>>(ei, E);
    kGather<<<(NN * 32 + 255) / 256, 256>>>(x);
    kPrep<<<(NN * 32 + DD * 64 + 255) / 256, 256>>>(x, Wl, Wr);
    kGemm<<<(NN + MTILE - 1) / MTILE, 256, SMEM_G>>>(bl, batch);
    kStats<<<(GG * DD + 255) / 256, 256>>>(ms);
    kFinal<<<(NN * 32 + 255) / 256, 256>>>(x, batch, gw, gb, out);
}

// round 6
// speedup vs baseline: 1.7062x; 1.0182x over previous
#include <cuda_runtime.h>
#include <math.h>
#include <stdint.h>

// Problem constants (fixed shapes from the reference)
#define NN 50000
#define EE 600000
#define DD 128
#define GG 8
#define GN_EPS 1e-5f
#define MTILE 128
#define NB ((NN + 1023) / 1024)   // 49 scan blocks

// ---------------- scratch (device globals; no cudaMalloc allowed) ----------
__device__ float g_agg[NN * DD];     // gathered mean, tf32-rounded
__device__ float g_wt[DD * 256];     // fused weights [n][k0..255] tf32-rounded
__device__ float g_f[NN * DD];       // post-GELU features
__device__ float g_sum[GG * DD];
__device__ float g_sumsq[GG * DD];
__device__ float g_cnt[GG];
__device__ int   g_degi[NN];
__device__ int   g_off[NN];
__device__ int   g_cur[NN];
__device__ int   g_csr[EE];
__device__ int   g_bsum[NB];

// ---------------- helpers ----------------
__device__ __forceinline__ uint32_t smem_u32(const void* p) {
    uint32_t a;
    asm("{ .reg .u64 t; cvta.to.shared.u64 t, %1; cvt.u32.u64 %0, t; }" : "=r"(a) : "l"(p));
    return a;
}
__device__ __forceinline__ void red_add_v2(float* p, float2 v) {
    size_t gp = __cvta_generic_to_global(p);
    asm volatile("red.global.add.v2.f32 [%0], {%1,%2};"
                 :: "l"(gp), "f"(v.x), "f"(v.y) : "memory");
}
__device__ __forceinline__ float gelu_exact(float v) {
    return 0.5f * v * (1.0f + erff(v * 0.70710678118654752f));
}
__device__ __forceinline__ float cvt_tf32(float f) {
    uint32_t u;
    asm("cvt.rna.satfinite.tf32.f32 %0, %1;" : "=r"(u) : "f"(f));
    return __uint_as_float(u);
}
__device__ __forceinline__ uint32_t cvt_tf32_u(uint32_t b) {
    uint32_t u;
    asm("cvt.rna.satfinite.tf32.f32 %0, %1;" : "=r"(u) : "f"(__uint_as_float(b)));
    return u;
}
__device__ __forceinline__ float4 cvt_tf32x4(float4 v) {
    return make_float4(cvt_tf32(v.x), cvt_tf32(v.y), cvt_tf32(v.z), cvt_tf32(v.w));
}
__device__ __forceinline__ void cp16(uint32_t dst, const void* src, bool pred) {
    int sz = pred ? 16 : 0;
    asm volatile("cp.async.cg.shared.global [%0], [%1], 16, %2;"
                 :: "r"(dst), "l"(src), "r"(sz) : "memory");
}
__device__ __forceinline__ void cp_commit() {
    asm volatile("cp.async.commit_group;" ::: "memory");
}
template <int N>
__device__ __forceinline__ void cp_wait() {
    asm volatile("cp.async.wait_group %0;" :: "n"(N) : "memory");
}
__device__ __forceinline__ void mma_tf32(float* d, const uint32_t* a, const uint32_t* b) {
    asm volatile("mma.sync.aligned.m16n8k8.row.col.f32.tf32.tf32.f32 "
                 "{%0,%1,%2,%3}, {%4,%5,%6,%7}, {%8,%9}, {%0,%1,%2,%3};"
                 : "+f"(d[0]), "+f"(d[1]), "+f"(d[2]), "+f"(d[3])
                 : "r"(a[0]), "r"(a[1]), "r"(a[2]), "r"(a[3]), "r"(b[0]), "r"(b[1]));
}

// ---------------- K1: zero scratch + fuse/round weights ----------------
__global__ void kInit(const float* __restrict__ Wl, const float* __restrict__ Wr) {
    int i = blockIdx.x * blockDim.x + threadIdx.x;
    if (i < NN) g_degi[i] = 0;
    if (i < GG * DD) { g_sum[i] = 0.f; g_sumsq[i] = 0.f; }
    if (i < GG) g_cnt[i] = 0.f;
    if (i < DD * 64) {
        int n = i >> 6, c4 = i & 63;
        float4 v = (c4 < 32) ? ((const float4*)Wl)[n * 32 + c4]
                             : ((const float4*)Wr)[n * 32 + (c4 - 32)];
        ((float4*)g_wt)[i] = cvt_tf32x4(v);
    }
}

// ---------------- K2: degree histogram + per-graph node counts -------------
__global__ void kDegCnt(const int* __restrict__ ei, const int* __restrict__ batch, int E) {
    __shared__ float h[GG];
    if (threadIdx.x < GG) h[threadIdx.x] = 0.f;
    __syncthreads();
    int i = blockIdx.x * blockDim.x + threadIdx.x;
    if (i < E) atomicAdd(&g_degi[__ldg(ei + E + i)], 1);
    if (i < NN) atomicAdd(&h[__ldg(batch + i)], 1.f);
    __syncthreads();
    if (threadIdx.x < GG) atomicAdd(&g_cnt[threadIdx.x], h[threadIdx.x]);
}

// ---------------- K3a: block-local exclusive scan ----------------
__global__ void __launch_bounds__(1024) kScan1() {
    __shared__ int wsum[32];
    int lane = threadIdx.x & 31, w = threadIdx.x >> 5;
    int i = blockIdx.x * 1024 + threadIdx.x;
    int v = (i < NN) ? g_degi[i] : 0;
    int s = v;
#pragma unroll
    for (int d = 1; d < 32; d <<= 1) {
        int t = __shfl_up_sync(0xFFFFFFFF, s, d);
        if (lane >= d) s += t;
    }
    if (lane == 31) wsum[w] = s;
    __syncthreads();
    if (w == 0) {
        int t = wsum[lane];
#pragma unroll
        for (int d = 1; d < 32; d <<= 1) {
            int u = __shfl_up_sync(0xFFFFFFFF, t, d);
            if (lane >= d) t += u;
        }
        wsum[lane] = t;
    }
    __syncthreads();
    int excl = s - v + (w > 0 ? wsum[w - 1] : 0);
    if (i < NN) g_off[i] = excl;
    if (threadIdx.x == 1023) g_bsum[blockIdx.x] = wsum[31];
}

// ---------------- K3b: add block base (warp-0 sums preceding totals) ------
__global__ void __launch_bounds__(1024) kScan3() {
    __shared__ int sbase;
    int lane = threadIdx.x & 31;
    if (threadIdx.x < 32) {
        int v = 0;
        for (int j = lane; j < blockIdx.x; j += 32) v += __ldg(&g_bsum[j]);
#pragma unroll
        for (int d = 16; d; d >>= 1) v += __shfl_xor_sync(0xFFFFFFFF, v, d);
        if (lane == 0) sbase = v;
    }
    __syncthreads();
    int i = blockIdx.x * 1024 + threadIdx.x;
    if (i >= NN) return;
    int o = g_off[i] + sbase;
    g_off[i] = o;
    g_cur[i] = o;
}

// ---------------- K4: counting-sort edges into CSR ----------------
__global__ void kBuildCSR(const int* __restrict__ ei, int E) {
    int e = blockIdx.x * blockDim.x + threadIdx.x;
    if (e >= E) return;
    int dst = __ldg(ei + E + e);
    int pos = atomicAdd(&g_cur[dst], 1);
    g_csr[pos] = __ldg(ei + e);
}

// ---------------- K5: warp-per-node gather, scale, tf32-round -------------
__global__ void kGather(const float* __restrict__ x) {
    int node = (blockIdx.x * blockDim.x + threadIdx.x) >> 5;
    int lane = threadIdx.x & 31;
    if (node >= NN) return;
    int o0 = __ldg(&g_off[node]);
    int d  = __ldg(&g_degi[node]);
    float4 acc = make_float4(0.f, 0.f, 0.f, 0.f);
#pragma unroll 4
    for (int j = 0; j < d; j++) {
        int nb = __ldg(&g_csr[o0 + j]);
        float4 v = ((const float4*)x)[(size_t)nb * 32 + lane];
        acc.x += v.x; acc.y += v.y; acc.z += v.z; acc.w += v.w;
    }
    float iv = 1.0f / fmaxf((float)d, 1.0f);
    acc.x *= iv; acc.y *= iv; acc.z *= iv; acc.w *= iv;
    ((float4*)g_agg)[(size_t)node * 32 + lane] = cvt_tf32x4(acc);
}

// ---------------- K6: tf32 mma.sync GEMM 128x128 tile, K=256 ---------------
// Chunks 0-3: A from g_agg (pre-rounded). Chunks 4-7: A from raw x,
// tf32-rounded in registers after LDS (numerically identical to prepass).
#define ASTRIDE 36
#define BUF_BYTES (128 * ASTRIDE * 4)
#define SMEM_G (4 * BUF_BYTES)

__global__ void __launch_bounds__(256) kGemm(const float* __restrict__ x,
                                             const float* __restrict__ bl,
                                             const int* __restrict__ batch) {
    extern __shared__ char smem[];
    uint32_t sbase = smem_u32(smem);
    int tid = threadIdx.x, wid = tid >> 5, lane = tid & 31;
    int gid = lane >> 2, tidg = lane & 3;
    int wm = wid & 1, wn = wid >> 1;
    int row0 = blockIdx.x * MTILE;

    auto issue = [&](int c, int b) {
        const float* Asrc = (c < 4) ? g_agg : x;
#pragma unroll
        for (int i = 0; i < 4; i++) {
            int idx = i * 256 + tid;
            int m = idx >> 3, c4 = idx & 7;
            int gr = row0 + m;
            bool ok = gr < NN;
            const float4* src = (const float4*)Asrc + (size_t)(ok ? gr : 0) * 32 + (c & 3) * 8 + c4;
            cp16(sbase + b * BUF_BYTES + (m * ASTRIDE + c4 * 4) * 4, src, ok);
        }
#pragma unroll
        for (int i = 0; i < 4; i++) {
            int idx = i * 256 + tid;
            int n = idx >> 3, c4 = idx & 7;
            const float4* src = (const float4*)g_wt + n * 64 + c * 8 + c4;
            cp16(sbase + (2 + b) * BUF_BYTES + (n * ASTRIDE + c4 * 4) * 4, src, true);
        }
        cp_commit();
    };

    float acc[4][4][4];
#pragma unroll
    for (int mf = 0; mf < 4; mf++)
#pragma unroll
        for (int nf = 0; nf < 4; nf++)
#pragma unroll
            for (int i = 0; i < 4; i++) acc[mf][nf][i] = 0.f;

    issue(0, 0);
    for (int c = 0; c < 8; c++) {
        int b = c & 1;
        if (c < 7) issue(c + 1, b ^ 1);
        if (c < 7) cp_wait<1>(); else cp_wait<0>();
        __syncthreads();

        const float* sA = (const float*)(smem + b * BUF_BYTES);
        const float* sB = (const float*)(smem + (2 + b) * BUF_BYTES);
        bool xc = (c >= 4);
#pragma unroll
        for (int ks = 0; ks < 32; ks += 8) {
            uint32_t a[4][4], bf[4][2];
#pragma unroll
            for (int mf = 0; mf < 4; mf++) {
                int r = wm * 64 + mf * 16 + gid;
                a[mf][0] = __float_as_uint(sA[r * ASTRIDE + ks + tidg]);
                a[mf][1] = __float_as_uint(sA[(r + 8) * ASTRIDE + ks + tidg]);
                a[mf][2] = __float_as_uint(sA[r * ASTRIDE + ks + tidg + 4]);
                a[mf][3] = __float_as_uint(sA[(r + 8) * ASTRIDE + ks + tidg + 4]);
            }
            if (xc) {
#pragma unroll
                for (int mf = 0; mf < 4; mf++)
#pragma unroll
                    for (int i = 0; i < 4; i++)
                        a[mf][i] = cvt_tf32_u(a[mf][i]);
            }
#pragma unroll
            for (int nf = 0; nf < 4; nf++) {
                int n = wn * 32 + nf * 8 + gid;
                bf[nf][0] = __float_as_uint(sB[n * ASTRIDE + ks + tidg]);
                bf[nf][1] = __float_as_uint(sB[n * ASTRIDE + ks + tidg + 4]);
            }
#pragma unroll
            for (int mf = 0; mf < 4; mf++)
#pragma unroll
                for (int nf = 0; nf < 4; nf++)
                    mma_tf32(acc[mf][nf], a[mf], bf[nf]);
        }
        __syncthreads();
    }

    // Epilogue: bias + exact GELU -> g_f, fused GraphNorm sum/sumsq
    int rlast = min(row0 + 127, NN - 1);
    int g0 = __ldg(batch + row0);
    bool uni = (__ldg(batch + rlast) == g0);

    float2 s[4], q[4];
#pragma unroll
    for (int nf = 0; nf < 4; nf++) { s[nf] = make_float2(0.f, 0.f); q[nf] = make_float2(0.f, 0.f); }

#pragma unroll
    for (int nf = 0; nf < 4; nf++) {
        int col = wn * 32 + nf * 8 + 2 * tidg;
        float2 bv = *(const float2*)(bl + col);
#pragma unroll
        for (int mf = 0; mf < 4; mf++) {
#pragma unroll
            for (int half = 0; half < 2; half++) {
                int r = row0 + wm * 64 + mf * 16 + gid + half * 8;
                if (r < NN) {
                    float2 f;
                    f.x = gelu_exact(acc[mf][nf][2 * half + 0] + bv.x);
                    f.y = gelu_exact(acc[mf][nf][2 * half + 1] + bv.y);
                    *(float2*)(g_f + (size_t)r * DD + col) = f;
                    if (uni) {
                        s[nf].x += f.x; s[nf].y += f.y;
                        q[nf].x += f.x * f.x; q[nf].y += f.y * f.y;
                    } else {
                        int g = __ldg(batch + r);
                        atomicAdd(&g_sum[g * DD + col], f.x);
                        atomicAdd(&g_sum[g * DD + col + 1], f.y);
                        atomicAdd(&g_sumsq[g * DD + col], f.x * f.x);
                        atomicAdd(&g_sumsq[g * DD + col + 1], f.y * f.y);
                    }
                }
            }
        }
    }
    if (uni) {
#pragma unroll
        for (int nf = 0; nf < 4; nf++) {
#pragma unroll
            for (int d = 4; d < 32; d <<= 1) {
                s[nf].x += __shfl_xor_sync(0xFFFFFFFF, s[nf].x, d);
                s[nf].y += __shfl_xor_sync(0xFFFFFFFF, s[nf].y, d);
                q[nf].x += __shfl_xor_sync(0xFFFFFFFF, q[nf].x, d);
                q[nf].y += __shfl_xor_sync(0xFFFFFFFF, q[nf].y, d);
            }
        }
        if (gid == 0) {
#pragma unroll
            for (int nf = 0; nf < 4; nf++) {
                int col = wn * 32 + nf * 8 + 2 * tidg;
                red_add_v2(&g_sum[g0 * DD + col], s[nf]);
                red_add_v2(&g_sumsq[g0 * DD + col], q[nf]);
            }
        }
    }
}

// ---------------- K7: finalize (stats computed per-block in smem) ----------
__global__ void __launch_bounds__(1024) kFinal(const float* __restrict__ x,
                                               const int* __restrict__ batch,
                                               const float* __restrict__ gw,
                                               const float* __restrict__ gb,
                                               const float* __restrict__ ms,
                                               float* __restrict__ out) {
    __shared__ float s_tm[GG * DD];
    __shared__ float s_ts[GG * DD];
    for (int i = threadIdx.x; i < GG * DD; i += 1024) {
        int c = i & 127, g = i >> 7;
        float cnt = fmaxf(g_cnt[g], 1.0f);
        float m   = g_sum[i] / cnt;
        float ex2 = g_sumsq[i] / cnt;
        float sc  = __ldg(ms + c);
        float var = ex2 - (2.0f * sc - sc * sc) * m * m;
        s_tm[i] = sc * m;
        s_ts[i] = rsqrtf(fmaxf(var, 0.0f) + GN_EPS);
    }
    __syncthreads();

    int i4 = blockIdx.x * 1024 + threadIdx.x;
    if (i4 >= NN * 32) return;
    int row = i4 >> 5;
    int c4  = i4 & 31;
    int g = __ldg(batch + row);
    float4 f  = ((const float4*)g_f)[i4];
    float4 xv = ((const float4*)x)[i4];
    float4 tm = ((const float4*)s_tm)[g * 32 + c4];
    float4 ts = ((const float4*)s_ts)[g * 32 + c4];
    float4 wv = ((const float4*)gw)[c4];
    float4 bv = ((const float4*)gb)[c4];
    float4 o;
    o.x = (f.x - tm.x) * ts.x * wv.x + bv.x + xv.x;
    o.y = (f.y - tm.y) * ts.y * wv.y + bv.y + xv.y;
    o.z = (f.z - tm.z) * ts.z * wv.z + bv.z + xv.z;
    o.w = (f.w - tm.w) * ts.w * wv.w + bv.w + xv.w;
    ((float4*)out)[i4] = o;
}

// ---------------- launch ----------------
extern "C" void kernel_launch(void* const* d_in, const int* in_sizes, int n_in,
                              void* d_out, int out_size) {
    const float* x     = (const float*)d_in[0];
    const int*   ei    = (const int*)d_in[1];
    const int*   batch = (const int*)d_in[2];
    int E = in_sizes[1] / 2;

    int wi = (in_sizes[3] == DD * DD) ? 3 : 4;
    const float* Wl = (const float*)d_in[wi + 0];
    const float* bl = (const float*)d_in[wi + 1];
    const float* Wr = (const float*)d_in[wi + 2];
    const float* gw = (const float*)d_in[wi + 3];
    const float* gb = (const float*)d_in[wi + 4];
    const float* ms = (const float*)d_in[wi + 5];
    float* out = (float*)d_out;

    cudaFuncSetAttribute(kGemm, cudaFuncAttributeMaxDynamicSharedMemorySize, SMEM_G);

    kInit<<<(NN + 255) / 256, 256>>>(Wl, Wr);
    kDegCnt<<<((E > NN ? E : NN) + 255) / 256, 256>>>(ei, batch, E);
    kScan1<<<NB, 1024>>>();
    kScan3<<<NB, 1024>>>();
    kBuildCSR<<<(E + 255) / 256, 256>>>(ei, E);
    kGather<<<(NN * 32 + 255) / 256, 256>>>(x);
    kGemm<<<(NN + MTILE - 1) / MTILE, 256, SMEM_G>>>(x, bl, batch);
    kFinal<<<(NN * 32 + 1023) / 1024, 1024>>>(x, batch, gw, gb, ms, out);
}